// round 16
// baseline (speedup 1.0000x reference)
#include <cuda_runtime.h>
#include <cuda_bf16.h>
#include <cstdint>

#define BB 2048
#define TRIP 189

// ---------------- scratch (device globals: allocation-guard safe) ----------------
__device__ float g_h1[BB * 64];
__device__ float g_h2[BB * 256];
__device__ float g_h3[BB * 1024];
__device__ float g_h4[BB * 4096];
__device__ float g_t1[BB * 128 * 64];
__device__ float g_t2[BB * 256 * 64];
__device__ float g_sc[4096];
__device__ float g_sh[4096];
// split-bf16 operand buffers (reused across layers). Max: 129024 x 768
__device__ __nv_bfloat16 g_Eh[129024 * 768];
__device__ __nv_bfloat16 g_El[129024 * 768];
// batched weight splits, layer-segmented (w2,w3,w4,cw1,cw2,cw3)
#define WOFF_W2 0
#define WOFF_W3 16384
#define WOFF_W4 278528
#define WOFF_C1 4472832
#define WOFF_C2 4497408
#define WOFF_C3 4595712
#define WTOT 4988928
__device__ __nv_bfloat16 g_Wh[WTOT];
__device__ __nv_bfloat16 g_Wl[WTOT];

// ======================= base-ISA tensor helpers (sm_80+) =======================
__device__ __forceinline__ uint32_t smem_u32(const void* p) {
    uint32_t a;
    asm("{ .reg .u64 t; cvta.to.shared.u64 t, %1; cvt.u32.u64 %0, t; }"
        : "=r"(a) : "l"(p));
    return a;
}
#define LDSM4(r0, r1, r2, r3, addr)                                             \
    asm volatile("ldmatrix.sync.aligned.m8n8.x4.shared.b16 {%0,%1,%2,%3}, [%4];"\
                 : "=r"(r0), "=r"(r1), "=r"(r2), "=r"(r3) : "r"(addr))
#define MMA16816(d, a, b)                                                       \
    asm volatile("mma.sync.aligned.m16n8k16.row.col.f32.bf16.bf16.f32 "         \
                 "{%0,%1,%2,%3}, {%4,%5,%6,%7}, {%8,%9}, {%0,%1,%2,%3};"        \
                 : "+f"((d)[0]), "+f"((d)[1]), "+f"((d)[2]), "+f"((d)[3])       \
                 : "r"((a)[0]), "r"((a)[1]), "r"((a)[2]), "r"((a)[3]),          \
                   "r"((b)[0]), "r"((b)[1]))
#define CP_ASYNC16(dst, src)                                                    \
    asm volatile("cp.async.cg.shared.global [%0], [%1], 16;" :: "r"(dst), "l"(src))
#define CP_COMMIT() asm volatile("cp.async.commit_group;" ::: "memory")
#define CP_WAIT1() asm volatile("cp.async.wait_group 1;" ::: "memory")
#define CP_WAIT0() asm volatile("cp.async.wait_group 0;" ::: "memory")

__device__ __forceinline__ int swz(int off) { return off ^ ((off >> 3) & 0x70); }

// ======================= mma GEMM: C(M,Ntot) = A(M,K) @ B(Ntot,K)^T ============
// split-bf16 3-pass (Ah*Bh + Ah*Bl + Al*Bh). CTA tile 256x128, 256 threads,
// warp tile 64x64 (4Mx2N) -> 85.3 smem-bytes per MMA. (R14 config: best measured.)
// Per K-chunk of 64: load {Ah(256x64), Al, Bh(128x64), Bl} once, double-buffered
// (2 x 96KB smem), run all 3 passes from smem with register fragment reuse.
// Buffer layout: Ah@0(32K) Al@32768 Bh@65536(16K) Bl@81920; stride 98304.
// EPI 0: out row-major (M,Ntot), += bias[col]
// EPI 1: conv: row r=(b*63+m); out[b][o][m+1] = v + bias[o]; out[b][o][0] = 0
#define GSM_TOTAL 196608

template <int ROWS>
__device__ __forceinline__ void cp_tileT(const __nv_bfloat16* __restrict__ src,
                                         int row0, int K, int kc, uint32_t sdst,
                                         int tid) {
#pragma unroll
    for (int i = 0; i < ROWS / 32; i++) {
        int lin = tid + i * 256;
        int r = lin >> 3, c16 = (lin & 7) * 16;
        const char* g = (const char*)(src + (size_t)(row0 + r) * K + kc * 64) + c16;
        CP_ASYNC16(sdst + swz(r * 128 + c16), g);
    }
}

__device__ __forceinline__ void load_chunk(const __nv_bfloat16* Ah,
                                           const __nv_bfloat16* Al,
                                           const __nv_bfloat16* Bh,
                                           const __nv_bfloat16* Bl, int bm, int bn,
                                           int K, int kc, uint32_t base, int tid) {
    cp_tileT<256>(Ah, bm, K, kc, base + 0, tid);
    cp_tileT<256>(Al, bm, K, kc, base + 32768, tid);
    cp_tileT<128>(Bh, bn, K, kc, base + 65536, tid);
    cp_tileT<128>(Bl, bn, K, kc, base + 81920, tid);
    CP_COMMIT();
}

template <int EPI>
__global__ __launch_bounds__(256) void mma_gemm(
    const __nv_bfloat16* __restrict__ Ah, const __nv_bfloat16* __restrict__ Al,
    const __nv_bfloat16* __restrict__ Bh, const __nv_bfloat16* __restrict__ Bl,
    const float* __restrict__ bias, float* __restrict__ out, int K, int Ntot) {
    extern __shared__ __align__(1024) char smem[];
    uint32_t sb = smem_u32(smem);
    int tid = threadIdx.x, wid = tid >> 5, lane = tid & 31;
    int bn = blockIdx.x * 128, bm = blockIdx.y * 256;
    int mw = wid >> 1, nw = wid & 1;  // warp grid 4 (M) x 2 (N)
    int m_base = mw * 64, n_base = nw * 64;

    const int KC = K >> 6;

    float acc[4][8][4];
#pragma unroll
    for (int mt = 0; mt < 4; mt++)
#pragma unroll
        for (int nt = 0; nt < 8; nt++)
#pragma unroll
            for (int q = 0; q < 4; q++) acc[mt][nt][q] = 0.f;

    int a_row = (lane & 15);
    int a_colsel = (lane & 16) ? 16 : 0;
    int b_row = (lane & 7) + ((lane & 16) ? 8 : 0);
    int b_colsel = (lane & 8) ? 16 : 0;

    load_chunk(Ah, Al, Bh, Bl, bm, bn, K, 0, sb, tid);
    if (KC > 1) load_chunk(Ah, Al, Bh, Bl, bm, bn, K, 1, sb + 98304, tid);

    for (int kc = 0; kc < KC; kc++) {
        int buf = kc & 1;
        if (kc < KC - 1) CP_WAIT1();
        else CP_WAIT0();
        __syncthreads();

        uint32_t base = sb + buf * 98304;
#pragma unroll
        for (int kk = 0; kk < 4; kk++) {
            uint32_t af[4][4];
            uint32_t bh_[8][2];
            uint32_t bl_[8][2];
            // load A-hi + B-hi, pass 0: Ah*Bh
#pragma unroll
            for (int mt = 0; mt < 4; mt++) {
                int off = (m_base + mt * 16 + a_row) * 128 + kk * 32 + a_colsel;
                LDSM4(af[mt][0], af[mt][1], af[mt][2], af[mt][3],
                      base + 0 + swz(off));
            }
#pragma unroll
            for (int np = 0; np < 4; np++) {
                int off = (n_base + np * 16 + b_row) * 128 + kk * 32 + b_colsel;
                LDSM4(bh_[2 * np][0], bh_[2 * np][1], bh_[2 * np + 1][0],
                      bh_[2 * np + 1][1], base + 65536 + swz(off));
            }
#pragma unroll
            for (int mt = 0; mt < 4; mt++)
#pragma unroll
                for (int nt = 0; nt < 8; nt++) MMA16816(acc[mt][nt], af[mt], bh_[nt]);
            // load B-lo, pass 1: Ah*Bl (reuse af)
#pragma unroll
            for (int np = 0; np < 4; np++) {
                int off = (n_base + np * 16 + b_row) * 128 + kk * 32 + b_colsel;
                LDSM4(bl_[2 * np][0], bl_[2 * np][1], bl_[2 * np + 1][0],
                      bl_[2 * np + 1][1], base + 81920 + swz(off));
            }
#pragma unroll
            for (int mt = 0; mt < 4; mt++)
#pragma unroll
                for (int nt = 0; nt < 8; nt++) MMA16816(acc[mt][nt], af[mt], bl_[nt]);
            // load A-lo into af, pass 2: Al*Bh (reuse bh_)
#pragma unroll
            for (int mt = 0; mt < 4; mt++) {
                int off = (m_base + mt * 16 + a_row) * 128 + kk * 32 + a_colsel;
                LDSM4(af[mt][0], af[mt][1], af[mt][2], af[mt][3],
                      base + 32768 + swz(off));
            }
#pragma unroll
            for (int mt = 0; mt < 4; mt++)
#pragma unroll
                for (int nt = 0; nt < 8; nt++) MMA16816(acc[mt][nt], af[mt], bh_[nt]);
        }
        __syncthreads();
        if (kc + 2 < KC)
            load_chunk(Ah, Al, Bh, Bl, bm, bn, K, kc + 2, sb + buf * 98304, tid);
    }

    // ---------------- epilogue ----------------
    if (EPI == 0) {
#pragma unroll
        for (int mt = 0; mt < 4; mt++) {
            int r0 = bm + m_base + mt * 16 + (lane >> 2);
#pragma unroll
            for (int nt = 0; nt < 8; nt++) {
                int cidx = bn + n_base + nt * 8 + (lane & 3) * 2;
                float bx = __ldg(&bias[cidx]), by = __ldg(&bias[cidx + 1]);
                float2 v0 = {acc[mt][nt][0] + bx, acc[mt][nt][1] + by};
                float2 v1 = {acc[mt][nt][2] + bx, acc[mt][nt][3] + by};
                *(float2*)(out + (size_t)r0 * Ntot + cidx) = v0;
                *(float2*)(out + (size_t)(r0 + 8) * Ntot + cidx) = v1;
            }
        }
    } else {
        const int PAD = 129;
        float* S = (float*)smem;
        __syncthreads();
#pragma unroll
        for (int mt = 0; mt < 4; mt++) {
            int r0 = m_base + mt * 16 + (lane >> 2);
#pragma unroll
            for (int nt = 0; nt < 8; nt++) {
                int cidx = n_base + nt * 8 + (lane & 3) * 2;
                S[r0 * PAD + cidx] = acc[mt][nt][0];
                S[r0 * PAD + cidx + 1] = acc[mt][nt][1];
                S[(r0 + 8) * PAD + cidx] = acc[mt][nt][2];
                S[(r0 + 8) * PAD + cidx + 1] = acc[mt][nt][3];
            }
        }
        __syncthreads();
        for (int e = tid; e < 256 * 128; e += 256) {
            int o = e >> 8;       // 0..127
            int lr = e & 255;     // consecutive tid -> consecutive rows
            int r = bm + lr;
            int b = r / 63;
            int m = r - b * 63;
            int oo = bn + o;
            float v = S[lr * PAD + o] + __ldg(&bias[oo]);
            float* ob = out + (size_t)b * Ntot * 64 + (size_t)oo * 64;
            ob[m + 1] = v;
            if (m == 0) ob[0] = 0.f;
        }
    }
}

// ======================= prep kernels =======================
// ONE batched weight split for all 6 layers (layer-segmented output buffer).
struct WSrc {
    const float* p[6];
};
__global__ void wsplit_all(WSrc srcs, __nv_bfloat16* __restrict__ wh,
                           __nv_bfloat16* __restrict__ wl) {
    const int offs[7] = {WOFF_W2, WOFF_W3, WOFF_W4, WOFF_C1, WOFF_C2, WOFF_C3, WTOT};
    int i = blockIdx.x * 256 + threadIdx.x;
    if (i >= WTOT) return;
    int s = 0;
#pragma unroll
    for (int j = 1; j < 6; j++)
        if (i >= offs[j]) s = j;
    float v = srcs.p[s][i - offs[s]];
    __nv_bfloat16 h = __float2bfloat16(v);
    wh[i] = h;
    wl[i] = __float2bfloat16(v - __bfloat162float(h));
}

__global__ void actsplit_kernel(const float* __restrict__ in,
                                const float* __restrict__ sc,
                                const float* __restrict__ sh,
                                __nv_bfloat16* __restrict__ ah,
                                __nv_bfloat16* __restrict__ al, int Kmask, int n) {
    int i = blockIdx.x * 256 + threadIdx.x;
    if (i >= n) return;
    int c = i & Kmask;
    float v = fmaf(sc[c], in[i], sh[c]);
    v = v > 0.f ? v : 0.01f * v;
    __nv_bfloat16 h = __float2bfloat16(v);
    ah[i] = h;
    al[i] = __float2bfloat16(v - __bfloat162float(h));
}

// gather + normalize + lrelu + bf16 split -> E(b*63+m, 3*CIN)
// MODE 0: per-feature affine sc/sh. MODE 1: per-sample tree-norm, with the
// mean/unbiased-std computed IN-BLOCK from the smem-staged x[b] (fused tnstats).
template <int CIN, int MODE>
__global__ __launch_bounds__(256) void gather_kernel(
    const float* __restrict__ in, const int* __restrict__ idx,
    const float* __restrict__ sc, const float* __restrict__ sh,
    __nv_bfloat16* __restrict__ Eh, __nv_bfloat16* __restrict__ El) {
    extern __shared__ float xs[];
    __shared__ int sidx[TRIP];
    __shared__ float rs[256], rq[256];
    const int K = 3 * CIN;
    const int NEL = CIN * 64;
    int b = blockIdx.x, tid = threadIdx.x;
    for (int j = tid; j < TRIP; j += 256) sidx[j] = idx[b * TRIP + j];
    const float* xb = in + (size_t)b * NEL;
    if (MODE == 0) {
        for (int i = tid; i < NEL; i += 256) {
            float v = fmaf(__ldg(&sc[i]), xb[i], __ldg(&sh[i]));
            v = v > 0.f ? v : 0.01f * v;
            xs[i] = v;
        }
        __syncthreads();
    } else {
        float s = 0.f, q = 0.f;
        for (int i = tid; i < NEL; i += 256) {
            float v = xb[i];
            xs[i] = v;
            s += v;
            q += v * v;
        }
        rs[tid] = s;
        rq[tid] = q;
        __syncthreads();
        for (int st = 128; st > 0; st >>= 1) {
            if (tid < st) {
                rs[tid] += rs[tid + st];
                rq[tid] += rq[tid + st];
            }
            __syncthreads();
        }
        float m = rs[0] / (float)NEL;
        float var = (rq[0] - (float)NEL * m * m) / (float)(NEL - 1);
        var = fmaxf(var, 0.f);
        float r = 1.f / (sqrtf(var) + 1e-5f);
        for (int i = tid; i < NEL; i += 256) {
            float v = (xs[i] - m) * r;
            xs[i] = v > 0.f ? v : 0.01f * v;
        }
        __syncthreads();
    }
    const int KH = K >> 1;
    __nv_bfloat162* EH = (__nv_bfloat162*)Eh;
    __nv_bfloat162* EL = (__nv_bfloat162*)El;
    for (int f = tid; f < 63 * KH; f += 256) {
        int m = f / KH;
        int t = (f - m * KH) * 2;
        int c0 = t / 3, k0 = t - 3 * c0;
        int t1 = t + 1;
        int c1 = t1 / 3, k1 = t1 - 3 * c1;
        float e0 = xs[c0 * 64 + sidx[3 * m + k0]];
        float e1 = xs[c1 * 64 + sidx[3 * m + k1]];
        __nv_bfloat16 h0 = __float2bfloat16(e0), h1 = __float2bfloat16(e1);
        float l0 = e0 - __bfloat162float(h0);
        float l1 = e1 - __bfloat162float(h1);
        size_t off = ((size_t)(b * 63 + m) * K + t) >> 1;
        EH[off] = __halves2bfloat162(h0, h1);
        EL[off] = __halves2bfloat162(__float2bfloat16(l0), __float2bfloat16(l1));
    }
}

// ======================= fp32 MLP layer-1 GEMM (tiny) =======================
__global__ __launch_bounds__(256) void mlp_gemm0(
    const float* __restrict__ A, const float* __restrict__ W,
    const float* __restrict__ bias, float* __restrict__ P, int K, int N) {
    __shared__ float As[16][64];
    __shared__ float Bs[16][64];
    int tid = threadIdx.x;
    int bm = blockIdx.x * 64, bn = blockIdx.y * 64;
    int lr = tid >> 2, lk = (tid & 3) * 4;
    int tx = tid & 15, ty = tid >> 4;
    float acc[4][4];
#pragma unroll
    for (int r = 0; r < 4; r++)
#pragma unroll
        for (int c = 0; c < 4; c++) acc[r][c] = 0.f;
    for (int k0 = 0; k0 < K; k0 += 16) {
        float4 a = *(const float4*)(A + (size_t)(bm + lr) * K + k0 + lk);
        float4 w4 = *(const float4*)(W + (size_t)(bn + lr) * K + k0 + lk);
        As[lk + 0][lr] = a.x; As[lk + 1][lr] = a.y;
        As[lk + 2][lr] = a.z; As[lk + 3][lr] = a.w;
        Bs[lk + 0][lr] = w4.x; Bs[lk + 1][lr] = w4.y;
        Bs[lk + 2][lr] = w4.z; Bs[lk + 3][lr] = w4.w;
        __syncthreads();
#pragma unroll
        for (int kk = 0; kk < 16; kk++) {
            float4 av = *(const float4*)&As[kk][ty * 4];
            float4 bv = *(const float4*)&Bs[kk][tx * 4];
            acc[0][0] += av.x * bv.x; acc[0][1] += av.x * bv.y;
            acc[0][2] += av.x * bv.z; acc[0][3] += av.x * bv.w;
            acc[1][0] += av.y * bv.x; acc[1][1] += av.y * bv.y;
            acc[1][2] += av.y * bv.z; acc[1][3] += av.y * bv.w;
            acc[2][0] += av.z * bv.x; acc[2][1] += av.z * bv.y;
            acc[2][2] += av.z * bv.z; acc[2][3] += av.z * bv.w;
            acc[3][0] += av.w * bv.x; acc[3][1] += av.w * bv.y;
            acc[3][2] += av.w * bv.z; acc[3][3] += av.w * bv.w;
        }
        __syncthreads();
    }
#pragma unroll
    for (int r = 0; r < 4; r++) {
        int i = bm + ty * 4 + r;
#pragma unroll
        for (int c = 0; c < 4; c++) {
            int j = bn + tx * 4 + c;
            P[(size_t)i * N + j] = acc[r][c] + bias[j];
        }
    }
}

// ---------------- BN stats: per-column mean/var -> scale/shift ----------------
__global__ void bnstats_kernel(const float* __restrict__ P, int N,
                               const float* __restrict__ g,
                               const float* __restrict__ be,
                               float* __restrict__ sc, float* __restrict__ sh) {
    __shared__ float ss[8][32], sq[8][32];
    int c = blockIdx.x * 32 + threadIdx.x;
    float s = 0.f, q = 0.f;
    for (int r = threadIdx.y; r < BB; r += 8) {
        float v = P[(size_t)r * N + c];
        s += v;
        q += v * v;
    }
    ss[threadIdx.y][threadIdx.x] = s;
    sq[threadIdx.y][threadIdx.x] = q;
    __syncthreads();
    if (threadIdx.y == 0) {
#pragma unroll
        for (int y = 1; y < 8; y++) {
            s += ss[y][threadIdx.x];
            q += sq[y][threadIdx.x];
        }
        float m = s * (1.f / BB);
        float var = q * (1.f / BB) - m * m;
        float a = g[c] * rsqrtf(var + 1e-5f);
        sc[c] = a;
        sh[c] = be[c] - a * m;
    }
}

// ---------------- final fused tree-norm: stats + apply + lrelu, smem-staged ----
// one block per sample; n = 512*64 floats = 128KB smem
__global__ __launch_bounds__(256) void tnfinal_kernel(float* __restrict__ X, int n) {
    extern __shared__ float s[];
    __shared__ float rs[256], rq[256];
    int b = blockIdx.x, tid = threadIdx.x;
    float4* src = (float4*)(X + (size_t)b * n);
    float4* sv = (float4*)s;
    float ss = 0.f, qq = 0.f;
    int n4 = n >> 2;
    for (int i = tid; i < n4; i += 256) {
        float4 v = src[i];
        sv[i] = v;
        ss += v.x + v.y + v.z + v.w;
        qq += v.x * v.x + v.y * v.y + v.z * v.z + v.w * v.w;
    }
    rs[tid] = ss;
    rq[tid] = qq;
    __syncthreads();
    for (int st = 128; st > 0; st >>= 1) {
        if (tid < st) {
            rs[tid] += rs[tid + st];
            rq[tid] += rq[tid + st];
        }
        __syncthreads();
    }
    float m = rs[0] / (float)n;
    float var = (rq[0] - (float)n * m * m) / (float)(n - 1);
    var = fmaxf(var, 0.f);
    float r = 1.f / (sqrtf(var) + 1e-5f);
    for (int i = tid; i < n4; i += 256) {
        float4 v = sv[i];
        v.x = (v.x - m) * r; v.x = v.x > 0.f ? v.x : 0.01f * v.x;
        v.y = (v.y - m) * r; v.y = v.y > 0.f ? v.y : 0.01f * v.y;
        v.z = (v.z - m) * r; v.z = v.z > 0.f ? v.z : 0.01f * v.z;
        v.w = (v.w - m) * r; v.w = v.w > 0.f ? v.w : 0.01f * v.w;
        src[i] = v;
    }
}

// ======================= host launch =======================
extern "C" void kernel_launch(void* const* d_in, const int* in_sizes, int n_in,
                              void* d_out, int out_size) {
    const float* trees = (const float*)d_in[0];
    const int* indexes = (const int*)d_in[1];
    const float* w1 = (const float*)d_in[2];
    const float* b1 = (const float*)d_in[3];
    const float* g1 = (const float*)d_in[4];
    const float* be1 = (const float*)d_in[5];
    const float* w2 = (const float*)d_in[6];
    const float* b2 = (const float*)d_in[7];
    const float* g2 = (const float*)d_in[8];
    const float* be2 = (const float*)d_in[9];
    const float* w3 = (const float*)d_in[10];
    const float* b3 = (const float*)d_in[11];
    const float* g3 = (const float*)d_in[12];
    const float* be3 = (const float*)d_in[13];
    const float* w4 = (const float*)d_in[14];
    const float* b4 = (const float*)d_in[15];
    const float* g4 = (const float*)d_in[16];
    const float* be4 = (const float*)d_in[17];
    const float* cw1 = (const float*)d_in[18];
    const float* cb1 = (const float*)d_in[19];
    const float* cw2 = (const float*)d_in[20];
    const float* cb2 = (const float*)d_in[21];
    const float* cw3 = (const float*)d_in[22];
    const float* cb3 = (const float*)d_in[23];
    float* out = (float*)d_out;

    float *p_h1, *p_h2, *p_h3, *p_h4, *p_t1, *p_t2, *p_sc, *p_sh;
    __nv_bfloat16 *p_Eh, *p_El, *p_Wh, *p_Wl;
    cudaGetSymbolAddress((void**)&p_h1, g_h1);
    cudaGetSymbolAddress((void**)&p_h2, g_h2);
    cudaGetSymbolAddress((void**)&p_h3, g_h3);
    cudaGetSymbolAddress((void**)&p_h4, g_h4);
    cudaGetSymbolAddress((void**)&p_t1, g_t1);
    cudaGetSymbolAddress((void**)&p_t2, g_t2);
    cudaGetSymbolAddress((void**)&p_sc, g_sc);
    cudaGetSymbolAddress((void**)&p_sh, g_sh);
    cudaGetSymbolAddress((void**)&p_Eh, g_Eh);
    cudaGetSymbolAddress((void**)&p_El, g_El);
    cudaGetSymbolAddress((void**)&p_Wh, g_Wh);
    cudaGetSymbolAddress((void**)&p_Wl, g_Wl);

    cudaFuncSetAttribute(mma_gemm<0>, cudaFuncAttributeMaxDynamicSharedMemorySize, GSM_TOTAL);
    cudaFuncSetAttribute(mma_gemm<1>, cudaFuncAttributeMaxDynamicSharedMemorySize, GSM_TOTAL);
    cudaFuncSetAttribute(gather_kernel<256, 1>, cudaFuncAttributeMaxDynamicSharedMemorySize, 256 * 64 * 4);
    cudaFuncSetAttribute(tnfinal_kernel, cudaFuncAttributeMaxDynamicSharedMemorySize, 512 * 64 * 4);

    dim3 bst(32, 8);

    // ---- all weight splits in ONE launch, up-front ----
    WSrc ws;
    ws.p[0] = w2; ws.p[1] = w3; ws.p[2] = w4;
    ws.p[3] = cw1; ws.p[4] = cw2; ws.p[5] = cw3;
    wsplit_all<<<(WTOT + 255) / 256, 256>>>(ws, p_Wh, p_Wl);

    // ---- MLP layer 1 (fp32, tiny) ----
    mlp_gemm0<<<dim3(32, 1), 256>>>(trees, w1, b1, p_h1, 64, 64);
    bnstats_kernel<<<2, bst>>>(p_h1, 64, g1, be1, p_sc, p_sh);

    // ---- MLP layer 2: 2048x256, K=64 ----
    actsplit_kernel<<<(BB * 64 + 255) / 256, 256>>>(p_h1, p_sc, p_sh, p_Eh, p_El, 63, BB * 64);
    mma_gemm<0><<<dim3(2, 8), 256, GSM_TOTAL>>>(p_Eh, p_El, p_Wh + WOFF_W2, p_Wl + WOFF_W2, b2, p_h2, 64, 256);
    bnstats_kernel<<<8, bst>>>(p_h2, 256, g2, be2, p_sc, p_sh);

    // ---- MLP layer 3: 2048x1024, K=256 ----
    actsplit_kernel<<<(BB * 256 + 255) / 256, 256>>>(p_h2, p_sc, p_sh, p_Eh, p_El, 255, BB * 256);
    mma_gemm<0><<<dim3(8, 8), 256, GSM_TOTAL>>>(p_Eh, p_El, p_Wh + WOFF_W3, p_Wl + WOFF_W3, b3, p_h3, 256, 1024);
    bnstats_kernel<<<32, bst>>>(p_h3, 1024, g3, be3, p_sc, p_sh);

    // ---- MLP layer 4: 2048x4096, K=1024 ----
    actsplit_kernel<<<(BB * 1024 + 255) / 256, 256>>>(p_h3, p_sc, p_sh, p_Eh, p_El, 1023, BB * 1024);
    mma_gemm<0><<<dim3(32, 8), 256, GSM_TOTAL>>>(p_Eh, p_El, p_Wh + WOFF_W4, p_Wl + WOFF_W4, b4, p_h4, 1024, 4096);
    bnstats_kernel<<<128, bst>>>(p_h4, 4096, g4, be4, p_sc, p_sh);

    // ---- tree conv 1: M=129024, N=128, K=192 ----
    gather_kernel<64, 0><<<BB, 256, 64 * 64 * 4>>>(p_h4, indexes, p_sc, p_sh, p_Eh, p_El);
    mma_gemm<1><<<dim3(1, 504), 256, GSM_TOTAL>>>(p_Eh, p_El, p_Wh + WOFF_C1, p_Wl + WOFF_C1, cb1, p_t1, 192, 128);

    // ---- tree conv 2: N=256, K=384 (tree-norm of t1 fused into gather) ----
    gather_kernel<128, 1><<<BB, 256, 128 * 64 * 4>>>(p_t1, indexes, nullptr, nullptr, p_Eh, p_El);
    mma_gemm<1><<<dim3(2, 504), 256, GSM_TOTAL>>>(p_Eh, p_El, p_Wh + WOFF_C2, p_Wl + WOFF_C2, cb2, p_t2, 384, 256);

    // ---- tree conv 3: N=512, K=768 -> d_out (tree-norm of t2 fused into gather) ----
    gather_kernel<256, 1><<<BB, 256, 256 * 64 * 4>>>(p_t2, indexes, nullptr, nullptr, p_Eh, p_El);
    mma_gemm<1><<<dim3(4, 504), 256, GSM_TOTAL>>>(p_Eh, p_El, p_Wh + WOFF_C3, p_Wl + WOFF_C3, cb3, out, 768, 512);

    // ---- final tree-norm + lrelu, fused single pass ----
    tnfinal_kernel<<<BB, 256, 512 * 64 * 4>>>(out, 512 * 64);
}

// round 17
// speedup vs baseline: 1.0163x; 1.0163x over previous
#include <cuda_runtime.h>
#include <cuda_bf16.h>
#include <cstdint>

#define BB 2048
#define TRIP 189

// ---------------- scratch (device globals: allocation-guard safe) ----------------
__device__ float g_h1[BB * 64];
__device__ float g_h2[BB * 256];
__device__ float g_h3[BB * 1024];
__device__ float g_h4[BB * 4096];
__device__ float g_t1[BB * 128 * 64];
__device__ float g_t2[BB * 256 * 64];
__device__ float g_sc[4096];
__device__ float g_sh[4096];
// split-bf16 operand buffers (reused across layers). Max: 129024 x 768
__device__ __nv_bfloat16 g_Eh[129024 * 768];
__device__ __nv_bfloat16 g_El[129024 * 768];
__device__ __nv_bfloat16 g_Wh[4096 * 1024];
__device__ __nv_bfloat16 g_Wl[4096 * 1024];

// ======================= base-ISA tensor helpers (sm_80+) =======================
__device__ __forceinline__ uint32_t smem_u32(const void* p) {
    uint32_t a;
    asm("{ .reg .u64 t; cvta.to.shared.u64 t, %1; cvt.u32.u64 %0, t; }"
        : "=r"(a) : "l"(p));
    return a;
}
#define LDSM4(r0, r1, r2, r3, addr)                                             \
    asm volatile("ldmatrix.sync.aligned.m8n8.x4.shared.b16 {%0,%1,%2,%3}, [%4];"\
                 : "=r"(r0), "=r"(r1), "=r"(r2), "=r"(r3) : "r"(addr))
#define MMA16816(d, a, b)                                                       \
    asm volatile("mma.sync.aligned.m16n8k16.row.col.f32.bf16.bf16.f32 "         \
                 "{%0,%1,%2,%3}, {%4,%5,%6,%7}, {%8,%9}, {%0,%1,%2,%3};"        \
                 : "+f"((d)[0]), "+f"((d)[1]), "+f"((d)[2]), "+f"((d)[3])       \
                 : "r"((a)[0]), "r"((a)[1]), "r"((a)[2]), "r"((a)[3]),          \
                   "r"((b)[0]), "r"((b)[1]))
#define CP_ASYNC16(dst, src)                                                    \
    asm volatile("cp.async.cg.shared.global [%0], [%1], 16;" :: "r"(dst), "l"(src))
#define CP_COMMIT() asm volatile("cp.async.commit_group;" ::: "memory")
#define CP_WAIT1() asm volatile("cp.async.wait_group 1;" ::: "memory")
#define CP_WAIT0() asm volatile("cp.async.wait_group 0;" ::: "memory")

__device__ __forceinline__ int swz(int off) { return off ^ ((off >> 3) & 0x70); }

// ======================= mma GEMM: C(M,Ntot) = A(M,K) @ B(Ntot,K)^T ============
// split-bf16 3-pass (Ah*Bh + Ah*Bl + Al*Bh). CTA tile MTx128 (MT=256 default;
// MT=128 instantiation for small-M layers to fill the chip), 256 threads,
// warp grid 4Mx2N, warp tile (MT/4)x64. Per K-chunk of 64: load
// {Ah(MTx64), Al, Bh(128x64), Bl} once, double-buffered, all 3 passes from smem
// with register fragment reuse.
// Buffer layout: Ah@0, Al@MT*128, Bh@2*MT*128, Bl@+16384; stride 2*MT*128+32768.
// EPI 0: out row-major (M,Ntot), += bias[col]
// EPI 1: conv: row r=(b*63+m); out[b][o][m+1] = v + bias[o]; out[b][o][0] = 0
#define GSM_256 196608
#define GSM_128 131072

template <int ROWS>
__device__ __forceinline__ void cp_tileT(const __nv_bfloat16* __restrict__ src,
                                         int row0, int K, int kc, uint32_t sdst,
                                         int tid) {
#pragma unroll
    for (int i = 0; i < ROWS / 32; i++) {
        int lin = tid + i * 256;
        int r = lin >> 3, c16 = (lin & 7) * 16;
        const char* g = (const char*)(src + (size_t)(row0 + r) * K + kc * 64) + c16;
        CP_ASYNC16(sdst + swz(r * 128 + c16), g);
    }
}

template <int MT>
__device__ __forceinline__ void load_chunk(const __nv_bfloat16* Ah,
                                           const __nv_bfloat16* Al,
                                           const __nv_bfloat16* Bh,
                                           const __nv_bfloat16* Bl, int bm, int bn,
                                           int K, int kc, uint32_t base, int tid) {
    constexpr int AB = MT * 128;
    cp_tileT<MT>(Ah, bm, K, kc, base + 0, tid);
    cp_tileT<MT>(Al, bm, K, kc, base + AB, tid);
    cp_tileT<128>(Bh, bn, K, kc, base + 2 * AB, tid);
    cp_tileT<128>(Bl, bn, K, kc, base + 2 * AB + 16384, tid);
    CP_COMMIT();
}

template <int EPI, int MT>
__global__ __launch_bounds__(256) void mma_gemm(
    const __nv_bfloat16* __restrict__ Ah, const __nv_bfloat16* __restrict__ Al,
    const __nv_bfloat16* __restrict__ Bh, const __nv_bfloat16* __restrict__ Bl,
    const float* __restrict__ bias, float* __restrict__ out, int K, int Ntot) {
    extern __shared__ __align__(1024) char smem[];
    constexpr int AMT = MT / 64;              // m-tiles per warp
    constexpr int AB = MT * 128;              // A digit bytes per chunk
    constexpr int CH = 2 * AB + 32768;        // chunk stride
    uint32_t sb = smem_u32(smem);
    int tid = threadIdx.x, wid = tid >> 5, lane = tid & 31;
    int bn = blockIdx.x * 128, bm = blockIdx.y * MT;
    int mw = wid >> 1, nw = wid & 1;  // warp grid 4 (M) x 2 (N)
    int m_base = mw * (MT / 4), n_base = nw * 64;

    const int KC = K >> 6;

    float acc[AMT][8][4];
#pragma unroll
    for (int mt = 0; mt < AMT; mt++)
#pragma unroll
        for (int nt = 0; nt < 8; nt++)
#pragma unroll
            for (int q = 0; q < 4; q++) acc[mt][nt][q] = 0.f;

    int a_row = (lane & 15);
    int a_colsel = (lane & 16) ? 16 : 0;
    int b_row = (lane & 7) + ((lane & 16) ? 8 : 0);
    int b_colsel = (lane & 8) ? 16 : 0;

    load_chunk<MT>(Ah, Al, Bh, Bl, bm, bn, K, 0, sb, tid);
    if (KC > 1) load_chunk<MT>(Ah, Al, Bh, Bl, bm, bn, K, 1, sb + CH, tid);

    for (int kc = 0; kc < KC; kc++) {
        int buf = kc & 1;
        if (kc < KC - 1) CP_WAIT1();
        else CP_WAIT0();
        __syncthreads();

        uint32_t base = sb + buf * CH;
#pragma unroll
        for (int kk = 0; kk < 4; kk++) {
            uint32_t af[AMT][4];
            uint32_t bh_[8][2];
            uint32_t bl_[8][2];
            // load A-hi + B-hi, pass 0: Ah*Bh
#pragma unroll
            for (int mt = 0; mt < AMT; mt++) {
                int off = (m_base + mt * 16 + a_row) * 128 + kk * 32 + a_colsel;
                LDSM4(af[mt][0], af[mt][1], af[mt][2], af[mt][3],
                      base + 0 + swz(off));
            }
#pragma unroll
            for (int np = 0; np < 4; np++) {
                int off = (n_base + np * 16 + b_row) * 128 + kk * 32 + b_colsel;
                LDSM4(bh_[2 * np][0], bh_[2 * np][1], bh_[2 * np + 1][0],
                      bh_[2 * np + 1][1], base + 2 * AB + swz(off));
            }
#pragma unroll
            for (int mt = 0; mt < AMT; mt++)
#pragma unroll
                for (int nt = 0; nt < 8; nt++) MMA16816(acc[mt][nt], af[mt], bh_[nt]);
            // load B-lo, pass 1: Ah*Bl (reuse af)
#pragma unroll
            for (int np = 0; np < 4; np++) {
                int off = (n_base + np * 16 + b_row) * 128 + kk * 32 + b_colsel;
                LDSM4(bl_[2 * np][0], bl_[2 * np][1], bl_[2 * np + 1][0],
                      bl_[2 * np + 1][1], base + 2 * AB + 16384 + swz(off));
            }
#pragma unroll
            for (int mt = 0; mt < AMT; mt++)
#pragma unroll
                for (int nt = 0; nt < 8; nt++) MMA16816(acc[mt][nt], af[mt], bl_[nt]);
            // load A-lo into af, pass 2: Al*Bh (reuse bh_)
#pragma unroll
            for (int mt = 0; mt < AMT; mt++) {
                int off = (m_base + mt * 16 + a_row) * 128 + kk * 32 + a_colsel;
                LDSM4(af[mt][0], af[mt][1], af[mt][2], af[mt][3],
                      base + AB + swz(off));
            }
#pragma unroll
            for (int mt = 0; mt < AMT; mt++)
#pragma unroll
                for (int nt = 0; nt < 8; nt++) MMA16816(acc[mt][nt], af[mt], bh_[nt]);
        }
        __syncthreads();
        if (kc + 2 < KC)
            load_chunk<MT>(Ah, Al, Bh, Bl, bm, bn, K, kc + 2, sb + buf * CH, tid);
    }

    // ---------------- epilogue ----------------
    if (EPI == 0) {
#pragma unroll
        for (int mt = 0; mt < AMT; mt++) {
            int r0 = bm + m_base + mt * 16 + (lane >> 2);
#pragma unroll
            for (int nt = 0; nt < 8; nt++) {
                int cidx = bn + n_base + nt * 8 + (lane & 3) * 2;
                float bx = __ldg(&bias[cidx]), by = __ldg(&bias[cidx + 1]);
                float2 v0 = {acc[mt][nt][0] + bx, acc[mt][nt][1] + by};
                float2 v1 = {acc[mt][nt][2] + bx, acc[mt][nt][3] + by};
                *(float2*)(out + (size_t)r0 * Ntot + cidx) = v0;
                *(float2*)(out + (size_t)(r0 + 8) * Ntot + cidx) = v1;
            }
        }
    } else {
        const int PAD = 129;
        float* S = (float*)smem;
        __syncthreads();
#pragma unroll
        for (int mt = 0; mt < AMT; mt++) {
            int r0 = m_base + mt * 16 + (lane >> 2);
#pragma unroll
            for (int nt = 0; nt < 8; nt++) {
                int cidx = n_base + nt * 8 + (lane & 3) * 2;
                S[r0 * PAD + cidx] = acc[mt][nt][0];
                S[r0 * PAD + cidx + 1] = acc[mt][nt][1];
                S[(r0 + 8) * PAD + cidx] = acc[mt][nt][2];
                S[(r0 + 8) * PAD + cidx + 1] = acc[mt][nt][3];
            }
        }
        __syncthreads();
        for (int e = tid; e < MT * 128; e += 256) {
            int o = e / MT;       // output channel within N-group
            int lr = e - o * MT;  // consecutive tid -> consecutive rows
            int r = bm + lr;
            int b = r / 63;
            int m = r - b * 63;
            int oo = bn + o;
            float v = S[lr * PAD + o] + __ldg(&bias[oo]);
            float* ob = out + (size_t)b * Ntot * 64 + (size_t)oo * 64;
            ob[m + 1] = v;
            if (m == 0) ob[0] = 0.f;
        }
    }
}

// ======================= prep kernels =======================
__global__ void wsplit_kernel(const float* __restrict__ w,
                              __nv_bfloat16* __restrict__ wh,
                              __nv_bfloat16* __restrict__ wl, int n) {
    int i = blockIdx.x * 256 + threadIdx.x;
    if (i >= n) return;
    float v = w[i];
    __nv_bfloat16 h = __float2bfloat16(v);
    wh[i] = h;
    wl[i] = __float2bfloat16(v - __bfloat162float(h));
}

__global__ void actsplit_kernel(const float* __restrict__ in,
                                const float* __restrict__ sc,
                                const float* __restrict__ sh,
                                __nv_bfloat16* __restrict__ ah,
                                __nv_bfloat16* __restrict__ al, int Kmask, int n) {
    int i = blockIdx.x * 256 + threadIdx.x;
    if (i >= n) return;
    int c = i & Kmask;
    float v = fmaf(sc[c], in[i], sh[c]);
    v = v > 0.f ? v : 0.01f * v;
    __nv_bfloat16 h = __float2bfloat16(v);
    ah[i] = h;
    al[i] = __float2bfloat16(v - __bfloat162float(h));
}

// gather + normalize + lrelu + bf16 split -> E(b*63+m, 3*CIN)
// MODE 0: per-feature affine sc/sh. MODE 1: per-sample tree-norm, with the
// mean/unbiased-std computed IN-BLOCK from the smem-staged x[b] (fused tnstats).
template <int CIN, int MODE>
__global__ __launch_bounds__(256) void gather_kernel(
    const float* __restrict__ in, const int* __restrict__ idx,
    const float* __restrict__ sc, const float* __restrict__ sh,
    __nv_bfloat16* __restrict__ Eh, __nv_bfloat16* __restrict__ El) {
    extern __shared__ float xs[];
    __shared__ int sidx[TRIP];
    __shared__ float rs[256], rq[256];
    const int K = 3 * CIN;
    const int NEL = CIN * 64;
    int b = blockIdx.x, tid = threadIdx.x;
    for (int j = tid; j < TRIP; j += 256) sidx[j] = idx[b * TRIP + j];
    const float* xb = in + (size_t)b * NEL;
    if (MODE == 0) {
        for (int i = tid; i < NEL; i += 256) {
            float v = fmaf(__ldg(&sc[i]), xb[i], __ldg(&sh[i]));
            v = v > 0.f ? v : 0.01f * v;
            xs[i] = v;
        }
        __syncthreads();
    } else {
        float s = 0.f, q = 0.f;
        for (int i = tid; i < NEL; i += 256) {
            float v = xb[i];
            xs[i] = v;
            s += v;
            q += v * v;
        }
        rs[tid] = s;
        rq[tid] = q;
        __syncthreads();
        for (int st = 128; st > 0; st >>= 1) {
            if (tid < st) {
                rs[tid] += rs[tid + st];
                rq[tid] += rq[tid + st];
            }
            __syncthreads();
        }
        float m = rs[0] / (float)NEL;
        float var = (rq[0] - (float)NEL * m * m) / (float)(NEL - 1);
        var = fmaxf(var, 0.f);
        float r = 1.f / (sqrtf(var) + 1e-5f);
        for (int i = tid; i < NEL; i += 256) {
            float v = (xs[i] - m) * r;
            xs[i] = v > 0.f ? v : 0.01f * v;
        }
        __syncthreads();
    }
    const int KH = K >> 1;
    __nv_bfloat162* EH = (__nv_bfloat162*)Eh;
    __nv_bfloat162* EL = (__nv_bfloat162*)El;
    for (int f = tid; f < 63 * KH; f += 256) {
        int m = f / KH;
        int t = (f - m * KH) * 2;
        int c0 = t / 3, k0 = t - 3 * c0;
        int t1 = t + 1;
        int c1 = t1 / 3, k1 = t1 - 3 * c1;
        float e0 = xs[c0 * 64 + sidx[3 * m + k0]];
        float e1 = xs[c1 * 64 + sidx[3 * m + k1]];
        __nv_bfloat16 h0 = __float2bfloat16(e0), h1 = __float2bfloat16(e1);
        float l0 = e0 - __bfloat162float(h0);
        float l1 = e1 - __bfloat162float(h1);
        size_t off = ((size_t)(b * 63 + m) * K + t) >> 1;
        EH[off] = __halves2bfloat162(h0, h1);
        EL[off] = __halves2bfloat162(__float2bfloat16(l0), __float2bfloat16(l1));
    }
}

// ======================= fp32 SIMT GEMM (small layers): P = act(A) @ W^T + b ====
// act = lrelu(sc[k]*x+sh[k]) if ACT. 64x64 tiles, grid (M/64, N/64).
template <int ACT>
__global__ __launch_bounds__(256) void mlp_gemm(
    const float* __restrict__ A, const float* __restrict__ W,
    const float* __restrict__ bias, const float* __restrict__ sc,
    const float* __restrict__ sh, float* __restrict__ P, int K, int N) {
    __shared__ float As[16][64];
    __shared__ float Bs[16][64];
    int tid = threadIdx.x;
    int bm = blockIdx.x * 64, bn = blockIdx.y * 64;
    int lr = tid >> 2, lk = (tid & 3) * 4;
    int tx = tid & 15, ty = tid >> 4;
    float acc[4][4];
#pragma unroll
    for (int r = 0; r < 4; r++)
#pragma unroll
        for (int c = 0; c < 4; c++) acc[r][c] = 0.f;
    for (int k0 = 0; k0 < K; k0 += 16) {
        float4 a = *(const float4*)(A + (size_t)(bm + lr) * K + k0 + lk);
        if (ACT) {
            float4 s4 = *(const float4*)(sc + k0 + lk);
            float4 h4 = *(const float4*)(sh + k0 + lk);
            a.x = fmaf(s4.x, a.x, h4.x); a.x = a.x > 0.f ? a.x : 0.01f * a.x;
            a.y = fmaf(s4.y, a.y, h4.y); a.y = a.y > 0.f ? a.y : 0.01f * a.y;
            a.z = fmaf(s4.z, a.z, h4.z); a.z = a.z > 0.f ? a.z : 0.01f * a.z;
            a.w = fmaf(s4.w, a.w, h4.w); a.w = a.w > 0.f ? a.w : 0.01f * a.w;
        }
        float4 w4 = *(const float4*)(W + (size_t)(bn + lr) * K + k0 + lk);
        As[lk + 0][lr] = a.x; As[lk + 1][lr] = a.y;
        As[lk + 2][lr] = a.z; As[lk + 3][lr] = a.w;
        Bs[lk + 0][lr] = w4.x; Bs[lk + 1][lr] = w4.y;
        Bs[lk + 2][lr] = w4.z; Bs[lk + 3][lr] = w4.w;
        __syncthreads();
#pragma unroll
        for (int kk = 0; kk < 16; kk++) {
            float4 av = *(const float4*)&As[kk][ty * 4];
            float4 bv = *(const float4*)&Bs[kk][tx * 4];
            acc[0][0] += av.x * bv.x; acc[0][1] += av.x * bv.y;
            acc[0][2] += av.x * bv.z; acc[0][3] += av.x * bv.w;
            acc[1][0] += av.y * bv.x; acc[1][1] += av.y * bv.y;
            acc[1][2] += av.y * bv.z; acc[1][3] += av.y * bv.w;
            acc[2][0] += av.z * bv.x; acc[2][1] += av.z * bv.y;
            acc[2][2] += av.z * bv.z; acc[2][3] += av.z * bv.w;
            acc[3][0] += av.w * bv.x; acc[3][1] += av.w * bv.y;
            acc[3][2] += av.w * bv.z; acc[3][3] += av.w * bv.w;
        }
        __syncthreads();
    }
#pragma unroll
    for (int r = 0; r < 4; r++) {
        int i = bm + ty * 4 + r;
#pragma unroll
        for (int c = 0; c < 4; c++) {
            int j = bn + tx * 4 + c;
            P[(size_t)i * N + j] = acc[r][c] + bias[j];
        }
    }
}

// ---------------- BN stats: per-column mean/var -> scale/shift ----------------
__global__ void bnstats_kernel(const float* __restrict__ P, int N,
                               const float* __restrict__ g,
                               const float* __restrict__ be,
                               float* __restrict__ sc, float* __restrict__ sh) {
    __shared__ float ss[8][32], sq[8][32];
    int c = blockIdx.x * 32 + threadIdx.x;
    float s = 0.f, q = 0.f;
    for (int r = threadIdx.y; r < BB; r += 8) {
        float v = P[(size_t)r * N + c];
        s += v;
        q += v * v;
    }
    ss[threadIdx.y][threadIdx.x] = s;
    sq[threadIdx.y][threadIdx.x] = q;
    __syncthreads();
    if (threadIdx.y == 0) {
#pragma unroll
        for (int y = 1; y < 8; y++) {
            s += ss[y][threadIdx.x];
            q += sq[y][threadIdx.x];
        }
        float m = s * (1.f / BB);
        float var = q * (1.f / BB) - m * m;
        float a = g[c] * rsqrtf(var + 1e-5f);
        sc[c] = a;
        sh[c] = be[c] - a * m;
    }
}

// ---------------- final fused tree-norm: stats + apply + lrelu, smem-staged ----
// one block per sample; n = 512*64 floats = 128KB smem
__global__ __launch_bounds__(256) void tnfinal_kernel(float* __restrict__ X, int n) {
    extern __shared__ float s[];
    __shared__ float rs[256], rq[256];
    int b = blockIdx.x, tid = threadIdx.x;
    float4* src = (float4*)(X + (size_t)b * n);
    float4* sv = (float4*)s;
    float ss = 0.f, qq = 0.f;
    int n4 = n >> 2;
    for (int i = tid; i < n4; i += 256) {
        float4 v = src[i];
        sv[i] = v;
        ss += v.x + v.y + v.z + v.w;
        qq += v.x * v.x + v.y * v.y + v.z * v.z + v.w * v.w;
    }
    rs[tid] = ss;
    rq[tid] = qq;
    __syncthreads();
    for (int st = 128; st > 0; st >>= 1) {
        if (tid < st) {
            rs[tid] += rs[tid + st];
            rq[tid] += rq[tid + st];
        }
        __syncthreads();
    }
    float m = rs[0] / (float)n;
    float var = (rq[0] - (float)n * m * m) / (float)(n - 1);
    var = fmaxf(var, 0.f);
    float r = 1.f / (sqrtf(var) + 1e-5f);
    for (int i = tid; i < n4; i += 256) {
        float4 v = sv[i];
        v.x = (v.x - m) * r; v.x = v.x > 0.f ? v.x : 0.01f * v.x;
        v.y = (v.y - m) * r; v.y = v.y > 0.f ? v.y : 0.01f * v.y;
        v.z = (v.z - m) * r; v.z = v.z > 0.f ? v.z : 0.01f * v.z;
        v.w = (v.w - m) * r; v.w = v.w > 0.f ? v.w : 0.01f * v.w;
        src[i] = v;
    }
}

// ======================= host launch =======================
extern "C" void kernel_launch(void* const* d_in, const int* in_sizes, int n_in,
                              void* d_out, int out_size) {
    const float* trees = (const float*)d_in[0];
    const int* indexes = (const int*)d_in[1];
    const float* w1 = (const float*)d_in[2];
    const float* b1 = (const float*)d_in[3];
    const float* g1 = (const float*)d_in[4];
    const float* be1 = (const float*)d_in[5];
    const float* w2 = (const float*)d_in[6];
    const float* b2 = (const float*)d_in[7];
    const float* g2 = (const float*)d_in[8];
    const float* be2 = (const float*)d_in[9];
    const float* w3 = (const float*)d_in[10];
    const float* b3 = (const float*)d_in[11];
    const float* g3 = (const float*)d_in[12];
    const float* be3 = (const float*)d_in[13];
    const float* w4 = (const float*)d_in[14];
    const float* b4 = (const float*)d_in[15];
    const float* g4 = (const float*)d_in[16];
    const float* be4 = (const float*)d_in[17];
    const float* cw1 = (const float*)d_in[18];
    const float* cb1 = (const float*)d_in[19];
    const float* cw2 = (const float*)d_in[20];
    const float* cb2 = (const float*)d_in[21];
    const float* cw3 = (const float*)d_in[22];
    const float* cb3 = (const float*)d_in[23];
    float* out = (float*)d_out;

    float *p_h1, *p_h2, *p_h3, *p_h4, *p_t1, *p_t2, *p_sc, *p_sh;
    __nv_bfloat16 *p_Eh, *p_El, *p_Wh, *p_Wl;
    cudaGetSymbolAddress((void**)&p_h1, g_h1);
    cudaGetSymbolAddress((void**)&p_h2, g_h2);
    cudaGetSymbolAddress((void**)&p_h3, g_h3);
    cudaGetSymbolAddress((void**)&p_h4, g_h4);
    cudaGetSymbolAddress((void**)&p_t1, g_t1);
    cudaGetSymbolAddress((void**)&p_t2, g_t2);
    cudaGetSymbolAddress((void**)&p_sc, g_sc);
    cudaGetSymbolAddress((void**)&p_sh, g_sh);
    cudaGetSymbolAddress((void**)&p_Eh, g_Eh);
    cudaGetSymbolAddress((void**)&p_El, g_El);
    cudaGetSymbolAddress((void**)&p_Wh, g_Wh);
    cudaGetSymbolAddress((void**)&p_Wl, g_Wl);

    cudaFuncSetAttribute(mma_gemm<0, 256>, cudaFuncAttributeMaxDynamicSharedMemorySize, GSM_256);
    cudaFuncSetAttribute(mma_gemm<1, 256>, cudaFuncAttributeMaxDynamicSharedMemorySize, GSM_256);
    cudaFuncSetAttribute(mma_gemm<0, 128>, cudaFuncAttributeMaxDynamicSharedMemorySize, GSM_128);
    cudaFuncSetAttribute(gather_kernel<256, 1>, cudaFuncAttributeMaxDynamicSharedMemorySize, 256 * 64 * 4);
    cudaFuncSetAttribute(tnfinal_kernel, cudaFuncAttributeMaxDynamicSharedMemorySize, 512 * 64 * 4);

    dim3 bst(32, 8);

    // ---- MLP layer 1 (fp32 SIMT, tiny) ----
    mlp_gemm<0><<<dim3(32, 1), 256>>>(trees, w1, b1, nullptr, nullptr, p_h1, 64, 64);
    bnstats_kernel<<<2, bst>>>(p_h1, 64, g1, be1, p_sc, p_sh);

    // ---- MLP layer 2 (fp32 SIMT, fused BN1-act; fills chip at 128 CTAs) ----
    mlp_gemm<1><<<dim3(32, 4), 256>>>(p_h1, w2, b2, p_sc, p_sh, p_h2, 64, 256);
    bnstats_kernel<<<8, bst>>>(p_h2, 256, g2, be2, p_sc, p_sh);

    // ---- MLP layer 3: 2048x1024, K=256 (MT=128 -> 128 CTAs, full chip) ----
    actsplit_kernel<<<(BB * 256 + 255) / 256, 256>>>(p_h2, p_sc, p_sh, p_Eh, p_El, 255, BB * 256);
    wsplit_kernel<<<(1024 * 256 + 255) / 256, 256>>>(w3, p_Wh, p_Wl, 1024 * 256);
    mma_gemm<0, 128><<<dim3(8, 16), 256, GSM_128>>>(p_Eh, p_El, p_Wh, p_Wl, b3, p_h3, 256, 1024);
    bnstats_kernel<<<32, bst>>>(p_h3, 1024, g3, be3, p_sc, p_sh);

    // ---- MLP layer 4: 2048x4096, K=1024 ----
    actsplit_kernel<<<(BB * 1024 + 255) / 256, 256>>>(p_h3, p_sc, p_sh, p_Eh, p_El, 1023, BB * 1024);
    wsplit_kernel<<<(4096 * 1024 + 255) / 256, 256>>>(w4, p_Wh, p_Wl, 4096 * 1024);
    mma_gemm<0, 256><<<dim3(32, 8), 256, GSM_256>>>(p_Eh, p_El, p_Wh, p_Wl, b4, p_h4, 1024, 4096);
    bnstats_kernel<<<128, bst>>>(p_h4, 4096, g4, be4, p_sc, p_sh);

    // ---- tree conv 1: M=129024, N=128, K=192 ----
    gather_kernel<64, 0><<<BB, 256, 64 * 64 * 4>>>(p_h4, indexes, p_sc, p_sh, p_Eh, p_El);
    wsplit_kernel<<<(128 * 192 + 255) / 256, 256>>>(cw1, p_Wh, p_Wl, 128 * 192);
    mma_gemm<1, 256><<<dim3(1, 504), 256, GSM_256>>>(p_Eh, p_El, p_Wh, p_Wl, cb1, p_t1, 192, 128);

    // ---- tree conv 2: N=256, K=384 (tree-norm of t1 fused into gather) ----
    gather_kernel<128, 1><<<BB, 256, 128 * 64 * 4>>>(p_t1, indexes, nullptr, nullptr, p_Eh, p_El);
    wsplit_kernel<<<(256 * 384 + 255) / 256, 256>>>(cw2, p_Wh, p_Wl, 256 * 384);
    mma_gemm<1, 256><<<dim3(2, 504), 256, GSM_256>>>(p_Eh, p_El, p_Wh, p_Wl, cb2, p_t2, 384, 256);

    // ---- tree conv 3: N=512, K=768 -> d_out (tree-norm of t2 fused into gather) ----
    gather_kernel<256, 1><<<BB, 256, 256 * 64 * 4>>>(p_t2, indexes, nullptr, nullptr, p_Eh, p_El);
    wsplit_kernel<<<(512 * 768 + 255) / 256, 256>>>(cw3, p_Wh, p_Wl, 512 * 768);
    mma_gemm<1, 256><<<dim3(4, 504), 256, GSM_256>>>(p_Eh, p_El, p_Wh, p_Wl, cb3, out, 768, 512);

    // ---- final tree-norm + lrelu, fused single pass ----
    tnfinal_kernel<<<BB, 256, 512 * 64 * 4>>>(out, 512 * 64);
}